// round 2
// baseline (speedup 1.0000x reference)
#include <cuda_runtime.h>
#include <cstdint>

#define L       8192
#define CH      16
#define BATCH   32
#define IGSTC   10
#define NSTEPS  100
#define HSTEP   0.01f
#define NCHUNK  (L / 8)          // 1024 chunks of 8 outputs
#define CPB     64               // chunks per block (256 threads / 4 groups)

typedef unsigned long long ull;

__device__ float g_z [(size_t)BATCH * CH * L];
__device__ float g_k1[(size_t)BATCH * CH * L];
__device__ float g_k2[(size_t)BATCH * CH * L];

__device__ __forceinline__ ull pk2(float lo, float hi) {
    ull r; asm("mov.b64 %0, {%1,%2};" : "=l"(r) : "f"(lo), "f"(hi)); return r;
}
__device__ __forceinline__ void upk2(ull a, float& lo, float& hi) {
    asm("mov.b64 {%0,%1}, %2;" : "=f"(lo), "=f"(hi) : "l"(a));
}
__device__ __forceinline__ void fma2(ull &acc, ull a, ull b) {
    asm("fma.rn.f32x2 %0, %1, %2, %0;" : "+l"(acc) : "l"(a), "l"(b));
}

// STAGE 1: out = B(z + h*conv(z))                      (conv input = zin)
// STAGE 2: out = B(0.75 z + 0.25 k1 + 0.25 h conv(k1)) (conv input = kin)
// STAGE 3: out = B(z/3 + 2 k2/3 + (2h/3) conv(k2))     (conv input = kin)
template<int STAGE>
__global__ void __launch_bounds__(256, 2)
stage_kernel(const float* __restrict__ zin, const float* __restrict__ kin,
             float* __restrict__ out, const float* __restrict__ W)
{
    // duplicated weight pairs for f32x2: wd4[(ci*16+co)*3 + k]
    //   k=0:(w0,w0,w1,w1) k=1:(w2,w2,w3,w3) k=2:(w4,w4,w4,w4)
    __shared__ float4 wd4[CH * CH * 3];

    const int tid = threadIdx.x;
    {
        int ci = tid >> 4, co = tid & 15;
        const float* wp = W + (co * CH + ci) * 5;
        float w0 = wp[0], w1 = wp[1], w2 = wp[2], w3 = wp[3], w4 = wp[4];
        float4* d = &wd4[(ci * CH + co) * 3];
        d[0] = make_float4(w0, w0, w1, w1);
        d[1] = make_float4(w2, w2, w3, w3);
        d[2] = make_float4(w4, w4, w4, w4);
    }
    __syncthreads();

    const int b    = blockIdx.y;
    const int grp  = tid & 3;             // cout group: couts 4g..4g+3
    const int slot = tid >> 2;            // chunk slot within block
    const int c    = blockIdx.x * CPB + slot;   // global chunk id
    const int xbase = c * 8;

    // conv window base (clamped at the two edge chunks; their outputs are
    // ghost cells and get discarded/overwritten anyway)
    int wb = xbase - 2;
    wb = wb < 0 ? 0 : (wb > L - 12 ? L - 12 : wb);

    const float* csrc = (STAGE == 1 ? zin : kin) + (size_t)b * CH * L;

    ull acc[4][4];
    #pragma unroll
    for (int q = 0; q < 4; ++q)
        #pragma unroll
        for (int j = 0; j < 4; ++j) acc[q][j] = 0ull;

    #pragma unroll 2
    for (int ci = 0; ci < CH; ++ci) {
        const float2* p = (const float2*)(csrc + ci * L + wb);
        float2 f0 = p[0], f1 = p[1], f2 = p[2], f3 = p[3], f4 = p[4], f5 = p[5];
        ull a0 = pk2(f0.x, f0.y), a1 = pk2(f1.x, f1.y), a2 = pk2(f2.x, f2.y);
        ull a3 = pk2(f3.x, f3.y), a4 = pk2(f4.x, f4.y), a5 = pk2(f5.x, f5.y);
        ull o0 = pk2(f0.y, f1.x), o1 = pk2(f1.y, f2.x), o2 = pk2(f2.y, f3.x);
        ull o3 = pk2(f3.y, f4.x), o4 = pk2(f4.y, f5.x);

        const ull* wrow = (const ull*)&wd4[(ci * CH + grp * 4) * 3];
        #pragma unroll
        for (int q = 0; q < 4; ++q) {
            ull w0 = wrow[q*6+0], w1 = wrow[q*6+1], w2 = wrow[q*6+2],
                w3 = wrow[q*6+3], w4 = wrow[q*6+4];
            ull* A = acc[q];
            fma2(A[0], a0, w0); fma2(A[0], o0, w1); fma2(A[0], a1, w2); fma2(A[0], o1, w3); fma2(A[0], a2, w4);
            fma2(A[1], a1, w0); fma2(A[1], o1, w1); fma2(A[1], a2, w2); fma2(A[1], o2, w3); fma2(A[1], a3, w4);
            fma2(A[2], a2, w0); fma2(A[2], o2, w1); fma2(A[2], a3, w2); fma2(A[2], o3, w3); fma2(A[2], a4, w4);
            fma2(A[3], a3, w0); fma2(A[3], o3, w1); fma2(A[3], a4, w2); fma2(A[3], o4, w3); fma2(A[3], a5, w4);
        }
    }

    // epilogue: res = ca*z + cb*k + cc*conv, then store with ghost handling.
    const float ca = (STAGE == 1) ? 1.0f      : (STAGE == 2) ? 0.75f        : (1.0f / 3.0f);
    const float cb = (STAGE == 1) ? 0.0f      : (STAGE == 2) ? 0.25f        : (2.0f / 3.0f);
    const float cc = (STAGE == 1) ? HSTEP     : (STAGE == 2) ? 0.25f*HSTEP  : (2.0f*HSTEP/3.0f);

    const bool store_ok = (c != 0) && (c != NCHUNK - 1);

    #pragma unroll
    for (int q = 0; q < 4; ++q) {
        const int co = 4 * grp + q;
        const size_t row = ((size_t)b * CH + co) * L;

        float cv[8];
        #pragma unroll
        for (int j = 0; j < 4; ++j) upk2(acc[q][j], cv[2*j], cv[2*j+1]);

        float4 za = *(const float4*)(zin + row + xbase);
        float4 zb = *(const float4*)(zin + row + xbase + 4);
        float zv[8] = {za.x, za.y, za.z, za.w, zb.x, zb.y, zb.z, zb.w};

        float kv[8];
        if (STAGE != 1) {
            float4 ka = *(const float4*)(kin + row + xbase);
            float4 kb = *(const float4*)(kin + row + xbase + 4);
            kv[0]=ka.x; kv[1]=ka.y; kv[2]=ka.z; kv[3]=ka.w;
            kv[4]=kb.x; kv[5]=kb.y; kv[6]=kb.z; kv[7]=kb.w;
        }

        float res[8];
        #pragma unroll
        for (int i = 0; i < 8; ++i) {
            if (STAGE == 1) res[i] = fmaf(cc, cv[i], zv[i]);
            else            res[i] = fmaf(ca, zv[i], fmaf(cb, kv[i], cc * cv[i]));
        }

        float* orow = out + row;
        if (store_ok) {
            *(float4*)(orow + xbase)     = make_float4(res[0], res[1], res[2], res[3]);
            *(float4*)(orow + xbase + 4) = make_float4(res[4], res[5], res[6], res[7]);
        }
        // ghost-cell extension: B(u)[x] = u[clamp(x, IGST, L-1-IGST)]
        if (c == 1) {              // this lane owns x=10 (res[2])
            float v = res[2];
            #pragma unroll
            for (int i = 0; i < IGSTC; ++i) orow[i] = v;
        }
        if (c == NCHUNK - 2) {     // this lane owns x=8181 (res[5])
            float v = res[5];
            #pragma unroll
            for (int i = 0; i < IGSTC; ++i) orow[L - IGSTC + i] = v;
        }
    }
}

extern "C" void kernel_launch(void* const* d_in, const int* in_sizes, int n_in,
                              void* d_out, int out_size) {
    const float* z0 = (const float*)d_in[0];
    const float* W  = (const float*)d_in[1];
    float* out = (float*)d_out;

    float *zscr, *k1, *k2;
    cudaGetSymbolAddress((void**)&zscr, g_z);
    cudaGetSymbolAddress((void**)&k1,   g_k1);
    cudaGetSymbolAddress((void**)&k2,   g_k2);

    dim3 grid(NCHUNK / CPB, BATCH);   // (16, 32) = 512 blocks
    const int nt = 256;

    for (int s = 0; s < NSTEPS; ++s) {
        const float* src;
        float* dst;
        if (s == 0)      { src = z0;   dst = zscr; }
        else if (s & 1)  { src = zscr; dst = out;  }
        else             { src = out;  dst = zscr; }

        stage_kernel<1><<<grid, nt>>>(src, nullptr, k1, W);
        stage_kernel<2><<<grid, nt>>>(src, k1, k2, W);
        stage_kernel<3><<<grid, nt>>>(src, k2, dst, W);
    }
}